// round 11
// baseline (speedup 1.0000x reference)
#include <cuda_runtime.h>
#include <cuda_fp16.h>
#include <cstdint>
#include <cstddef>

// ---------------------------------------------------------------------------
// Scratch:
//   g_fh: f1h [2][4096][256] fp16 at 0; f2h [2][5504][256] fp16 at 2,097,152
//         (f2 level row bases 0,4096,5120,5376; rows 5440..5503 stay zero)
//   g_corrh: [2][4096][5504] fp16 correlation volume
//   g_mask: per (b, m-tile) bitmask of needed n-tiles (43 bits used)
// ---------------------------------------------------------------------------
#define F1H_OFF ((size_t)0)
#define F2H_OFF ((size_t)2097152)
#define F2_BSTRIDE ((size_t)1409024)   // 5504*256
#define CORR_COLS 5504
__device__ __half g_fh[4915200];
__device__ __half g_corrh[45088768];
__device__ unsigned long long g_mask[64];

__device__ __forceinline__ uint32_t smem_u32(const void* p) {
    uint32_t a;
    asm("{ .reg .u64 t; cvta.to.shared.u64 t, %1; cvt.u32.u64 %0, t; }"
        : "=r"(a) : "l"(p));
    return a;
}

// ---------------------------------------------------------------------------
// Fused transpose+convert + needed-tile mask. Write phase vectorized (half2).
// ---------------------------------------------------------------------------
__global__ __launch_bounds__(256) void tconv_kernel(
    const float* __restrict__ f1, const float* __restrict__ f20,
    const float* __restrict__ f21, const float* __restrict__ f22,
    const float* __restrict__ f23, const float* __restrict__ coords) {
    __shared__ float tile[32][33];
    const int bx = blockIdx.x, bz = blockIdx.z;
    const int tid = threadIdx.x;
    const int tx = tid & 31, ty = tid >> 5;

    if (bx >= 298) {
        if (blockIdx.y != 0 || bz != 0) return;
        const int gw = (bx - 298) * 8 + ty;   // 0..63
        const int lane = tx;
        const int b = gw >> 5, mt = gw & 31;
        const int lb[4] = {0, 4096, 5120, 5376};
        unsigned long long m = 0ULL;
#pragma unroll
        for (int j = 0; j < 4; j++) {
            const int hw = mt * 128 + j * 32 + lane;
            const float x = coords[(size_t)b * 8192 + hw];
            const float y = coords[(size_t)b * 8192 + 4096 + hw];
#pragma unroll
            for (int l = 0; l < 4; l++) {
                const int W2 = 64 >> l;
                const float s = 1.0f / (float)(1 << l);
                const int x0 = (int)floorf(x * s);
                const int y0 = (int)floorf(y * s);
                const int gx0 = max(x0 - 4, 0), gx1 = min(x0 + 5, W2 - 1);
                const int gy0 = max(y0 - 4, 0), gy1 = min(y0 + 5, W2 - 1);
                if (gx0 > gx1 || gy0 > gy1) continue;
                const int t0 = (lb[l] + gy0 * W2 + gx0) >> 7;
                const int t1 = (lb[l] + gy1 * W2 + gx1) >> 7;
                m |= (((1ULL << (t1 - t0 + 1)) - 1ULL) << t0);
            }
        }
        unsigned lo = (unsigned)m, hi = (unsigned)(m >> 32);
#pragma unroll
        for (int o = 16; o; o >>= 1) {
            lo |= __shfl_xor_sync(0xffffffffu, lo, o);
            hi |= __shfl_xor_sync(0xffffffffu, hi, o);
        }
        if (lane == 0) g_mask[gw] = ((unsigned long long)hi << 32) | lo;
        return;
    }

    const float* src;
    int P, pBase;
    size_t dstOff, bStride;
    if (bx < 128)      { src = f1;  P = 4096; pBase = bx;       dstOff = F1H_OFF;                      bStride = 1048576; }
    else if (bx < 256) { src = f20; P = 4096; pBase = bx - 128; dstOff = F2H_OFF;                      bStride = F2_BSTRIDE; }
    else if (bx < 288) { src = f21; P = 1024; pBase = bx - 256; dstOff = F2H_OFF + (size_t)4096 * 256; bStride = F2_BSTRIDE; }
    else if (bx < 296) { src = f22; P = 256;  pBase = bx - 288; dstOff = F2H_OFF + (size_t)5120 * 256; bStride = F2_BSTRIDE; }
    else               { src = f23; P = 64;   pBase = bx - 296; dstOff = F2H_OFF + (size_t)5376 * 256; bStride = F2_BSTRIDE; }

    const float* s = src + (size_t)bz * 256 * P;
    __half* d = g_fh + dstOff + (size_t)bz * bStride;
    const int p0 = pBase * 32, c0 = blockIdx.y * 32;
#pragma unroll
    for (int k = 0; k < 4; k++)
        tile[ty + 8 * k][tx] = s[(size_t)(c0 + ty + 8 * k) * P + p0 + tx];
    __syncthreads();

    // write: 2 iters; thread -> pixel p = (tid>>4) + 16*it, channel pair c = tid&15
    const int cp = tid & 15, pr = tid >> 4;
#pragma unroll
    for (int it = 0; it < 2; it++) {
        const int p = pr + it * 16;
        const __half2 h = __floats2half2_rn(tile[2 * cp][p], tile[2 * cp + 1][p]);
        *(__half2*)(d + (size_t)(p0 + p) * 256 + c0 + 2 * cp) = h;
    }
}

// ---------------------------------------------------------------------------
// GEMM: per-tile grid (round-9 schedule), 128x128 tile, K=256 in 4 chunks,
// 2-stage cp.async pipeline (64KB smem) -> 3 CTAs/SM. 4 warps, warp tile 64x64.
// ---------------------------------------------------------------------------
#define STAGE_BYTES 32768
#define GEMM_SMEM   (2 * STAGE_BYTES)   // 65536

__device__ __forceinline__ void ldsm_x4(uint32_t (&r)[4], uint32_t addr) {
    asm volatile("ldmatrix.sync.aligned.m8n8.x4.shared.b16 {%0,%1,%2,%3}, [%4];"
                 : "=r"(r[0]), "=r"(r[1]), "=r"(r[2]), "=r"(r[3]) : "r"(addr));
}
__device__ __forceinline__ void mma16816(float (&d)[4], const uint32_t (&a)[4],
                                         uint32_t b0, uint32_t b1) {
    asm volatile(
        "mma.sync.aligned.m16n8k16.row.col.f32.f16.f16.f32 "
        "{%0,%1,%2,%3},{%4,%5,%6,%7},{%8,%9},{%0,%1,%2,%3};"
        : "+f"(d[0]), "+f"(d[1]), "+f"(d[2]), "+f"(d[3])
        : "r"(a[0]), "r"(a[1]), "r"(a[2]), "r"(a[3]), "r"(b0), "r"(b1));
}

__device__ __forceinline__ uint32_t sw_addr(uint32_t base, int row, int chunk) {
    return base + (uint32_t)row * 128u + (uint32_t)((chunk ^ (row & 7)) << 4);
}

__device__ __forceinline__ void load_chunk(const __half* __restrict__ A,
                                           const __half* __restrict__ B,
                                           uint32_t sbase, int stage, int ck, int tid) {
    const uint32_t aoff = sbase + stage * STAGE_BYTES;
    const uint32_t boff = aoff + 16384;
#pragma unroll
    for (int q = tid; q < 1024; q += 128) {
        const int r = q >> 3, c = q & 7;
        const uint32_t sa = sw_addr(aoff, r, c);
        const uint32_t sb = sw_addr(boff, r, c);
        const __half* ga = A + (size_t)r * 256 + ck * 64 + c * 8;
        const __half* gb = B + (size_t)r * 256 + ck * 64 + c * 8;
        asm volatile("cp.async.cg.shared.global [%0], [%1], 16;" :: "r"(sa), "l"(ga));
        asm volatile("cp.async.cg.shared.global [%0], [%1], 16;" :: "r"(sb), "l"(gb));
    }
    asm volatile("cp.async.commit_group;" ::: "memory");
}

__global__ void __launch_bounds__(128, 3) gemm_kernel() {
    const int nt = blockIdx.x, mt = blockIdx.y, b = blockIdx.z;
    if (!((g_mask[b * 32 + mt] >> nt) & 1ULL)) return;

    extern __shared__ char smraw[];
    const uint32_t sbase = smem_u32(smraw);
    const int tid = threadIdx.x, warp = tid >> 5, lane = tid & 31;

    const __half* A = g_fh + F1H_OFF + ((size_t)b * 4096 + (size_t)mt * 128) * 256;
    const __half* B = g_fh + F2H_OFF + (size_t)b * F2_BSTRIDE + (size_t)nt * 128 * 256;

    load_chunk(A, B, sbase, 0, 0, tid);

    const int wm = (warp & 1) * 64;
    const int wn = (warp >> 1) * 64;
    const int row_in = lane & 7;
    const int mat = lane >> 3;

    float acc[4][8][4];
#pragma unroll
    for (int mi = 0; mi < 4; mi++)
#pragma unroll
        for (int ni = 0; ni < 8; ni++)
#pragma unroll
            for (int j = 0; j < 4; j++) acc[mi][ni][j] = 0.0f;

#pragma unroll
    for (int ck = 0; ck < 4; ck++) {
        asm volatile("cp.async.wait_group 0;" ::: "memory");
        __syncthreads();
        if (ck + 1 < 4) load_chunk(A, B, sbase, (ck + 1) & 1, ck + 1, tid);

        const uint32_t aT = sbase + (ck & 1) * STAGE_BYTES;
        const uint32_t bT = aT + 16384;

#pragma unroll
        for (int ks = 0; ks < 4; ks++) {
            uint32_t af[4][4];
#pragma unroll
            for (int mi = 0; mi < 4; mi++) {
                const int row = wm + mi * 16 + (mat & 1) * 8 + row_in;
                ldsm_x4(af[mi], sw_addr(aT, row, ks * 2 + (mat >> 1)));
            }
            uint32_t bf[4][4];
#pragma unroll
            for (int bi = 0; bi < 4; bi++) {
                const int nrow = wn + bi * 16 + (mat >> 1) * 8 + row_in;
                ldsm_x4(bf[bi], sw_addr(bT, nrow, ks * 2 + (mat & 1)));
            }
#pragma unroll
            for (int mi = 0; mi < 4; mi++)
#pragma unroll
                for (int ni = 0; ni < 8; ni++) {
                    const uint32_t* bb = bf[ni >> 1];
                    if (ni & 1) mma16816(acc[mi][ni], af[mi], bb[2], bb[3]);
                    else        mma16816(acc[mi][ni], af[mi], bb[0], bb[1]);
                }
        }
    }

    const int g = lane >> 2, tg = lane & 3;
    __half* crow = g_corrh + ((size_t)b * 4096 + (size_t)mt * 128) * CORR_COLS +
                   (size_t)nt * 128;
#pragma unroll
    for (int mi = 0; mi < 4; mi++) {
#pragma unroll
        for (int ni = 0; ni < 8; ni++) {
            const int rm = wm + mi * 16 + g;
            const int cn = wn + ni * 8 + tg * 2;
            *(__half2*)(crow + (size_t)rm * CORR_COLS + cn) =
                __floats2half2_rn(acc[mi][ni][0], acc[mi][ni][1]);
            *(__half2*)(crow + (size_t)(rm + 8) * CORR_COLS + cn) =
                __floats2half2_rn(acc[mi][ni][2], acc[mi][ni][3]);
        }
    }
}

// ---------------------------------------------------------------------------
// Gather v2 (round-9 version, unchanged).
// ---------------------------------------------------------------------------
__global__ __launch_bounds__(256) void gather_kernel(const float* __restrict__ coords,
                                                     float* __restrict__ out) {
    __shared__ float dots[4][8][104];
    __shared__ float s_cx[8], s_cy[8];

    const int tid = threadIdx.x;
    const int pix0 = blockIdx.x * 8;
    const int b = pix0 >> 12;
    const int hw = pix0 & 4095;

    if (tid < 8) {
        s_cx[tid] = coords[(size_t)b * 8192 + hw + tid];
        s_cy[tid] = coords[(size_t)b * 8192 + 4096 + hw + tid];
    }
    __syncthreads();

    const int lvl_base[4] = {0, 4096, 5120, 5376};

#pragma unroll
    for (int it = 0; it < 16; it++) {
        const int e = tid + it * 256;           // e < 4096
        const int pt = e & 127;
        const int px = (e >> 7) & 7;
        const int lvl = e >> 10;
        if (pt < 100) {
            const int W2 = 64 >> lvl;
            const float scale = 1.0f / (float)(1 << lvl);
            const float x = s_cx[px] * scale;
            const float y = s_cy[px] * scale;
            const int x0 = (int)floorf(x);
            const int y0 = (int)floorf(y);
            const int gi = pt / 10;
            const int gj = pt - gi * 10;
            const int gx = x0 - 4 + gj;
            const int gy = y0 - 4 + gi;
            float v = 0.0f;
            if ((unsigned)gx < (unsigned)W2 && (unsigned)gy < (unsigned)W2)
                v = __half2float(g_corrh[((size_t)b * 4096 + hw + px) * CORR_COLS +
                                         lvl_base[lvl] + gy * W2 + gx]);
            dots[lvl][px][pt] = v;
        }
    }
    __syncthreads();

#pragma unroll
    for (int it = 0; it < 11; it++) {
        const int e = tid + it * 256;
        if (e < 2592) {
            const int lvl = e / 648;
            const int r = e - lvl * 648;
            const int k = r >> 3;
            const int px = r & 7;
            const int oi = k / 9;
            const int oj = k - oi * 9;
            const float scale = 1.0f / (float)(1 << lvl);
            const float x = s_cx[px] * scale;
            const float y = s_cy[px] * scale;
            const float fx = x - floorf(x);
            const float fy = y - floorf(y);
            const float w00 = (1.0f - fx) * (1.0f - fy);
            const float w10 = fx * (1.0f - fy);
            const float w01 = (1.0f - fx) * fy;
            const float w11 = fx * fy;
            const int base = oi * 10 + oj;
            const float* dp = dots[lvl][px];
            const float val = w00 * dp[base]      + w10 * dp[base + 1] +
                              w01 * dp[base + 10] + w11 * dp[base + 11];
            out[(size_t)(b * 324 + lvl * 81 + k) * 4096 + hw + px] = val * 0.0625f;
        }
    }
}

// ---------------------------------------------------------------------------
// Inputs: fmap1, fmap2_0..3, coords. Output [2,324,64,64] fp32.
// ---------------------------------------------------------------------------
extern "C" void kernel_launch(void* const* d_in, const int* in_sizes, int n_in,
                              void* d_out, int out_size) {
    const float* f1 = (const float*)d_in[0];
    const float* f2_0 = (const float*)d_in[1];
    const float* f2_1 = (const float*)d_in[2];
    const float* f2_2 = (const float*)d_in[3];
    const float* f2_3 = (const float*)d_in[4];
    const float* coords = (const float*)d_in[5];
    float* out = (float*)d_out;

    static bool attr_done = false;
    if (!attr_done) {
        cudaFuncSetAttribute(gemm_kernel, cudaFuncAttributeMaxDynamicSharedMemorySize,
                             GEMM_SMEM);
        attr_done = true;
    }

    tconv_kernel<<<dim3(306, 8, 2), 256>>>(f1, f2_0, f2_1, f2_2, f2_3, coords);
    gemm_kernel<<<dim3(43, 32, 2), 128, GEMM_SMEM>>>();
    gather_kernel<<<1024, 256>>>(coords, out);
}

// round 12
// speedup vs baseline: 1.3201x; 1.3201x over previous
#include <cuda_runtime.h>
#include <cuda_fp16.h>
#include <cstdint>
#include <cstddef>

// ---------------------------------------------------------------------------
// Scratch:
//   g_fh: f1h [2][4096][256] fp16 at 0; f2h [2][5504][256] fp16 at 2,097,152
//         (f2 level row bases 0,4096,5120,5376; rows 5440..5503 stay zero)
//   g_corrh: [2][4096][5504] fp16 correlation volume
//   g_mask: per (b, m-tile) bitmask of needed n-tiles (43 bits used)
// ---------------------------------------------------------------------------
#define F1H_OFF ((size_t)0)
#define F2H_OFF ((size_t)2097152)
#define F2_BSTRIDE ((size_t)1409024)   // 5504*256
#define CORR_COLS 5504
__device__ __half g_fh[4915200];
__device__ __half g_corrh[45088768];
__device__ unsigned long long g_mask[64];

__device__ __forceinline__ uint32_t smem_u32(const void* p) {
    uint32_t a;
    asm("{ .reg .u64 t; cvta.to.shared.u64 t, %1; cvt.u32.u64 %0, t; }"
        : "=r"(a) : "l"(p));
    return a;
}

// ---------------------------------------------------------------------------
// Fused transpose+convert + needed-tile mask. Vectorized half2 write phase
// (round-11 tconv: measured 9.47us vs 9.76us).
// ---------------------------------------------------------------------------
__global__ __launch_bounds__(256) void tconv_kernel(
    const float* __restrict__ f1, const float* __restrict__ f20,
    const float* __restrict__ f21, const float* __restrict__ f22,
    const float* __restrict__ f23, const float* __restrict__ coords) {
    __shared__ float tile[32][33];
    const int bx = blockIdx.x, bz = blockIdx.z;
    const int tid = threadIdx.x;
    const int tx = tid & 31, ty = tid >> 5;

    if (bx >= 298) {
        if (blockIdx.y != 0 || bz != 0) return;
        const int gw = (bx - 298) * 8 + ty;   // 0..63
        const int lane = tx;
        const int b = gw >> 5, mt = gw & 31;
        const int lb[4] = {0, 4096, 5120, 5376};
        unsigned long long m = 0ULL;
#pragma unroll
        for (int j = 0; j < 4; j++) {
            const int hw = mt * 128 + j * 32 + lane;
            const float x = coords[(size_t)b * 8192 + hw];
            const float y = coords[(size_t)b * 8192 + 4096 + hw];
#pragma unroll
            for (int l = 0; l < 4; l++) {
                const int W2 = 64 >> l;
                const float s = 1.0f / (float)(1 << l);
                const int x0 = (int)floorf(x * s);
                const int y0 = (int)floorf(y * s);
                const int gx0 = max(x0 - 4, 0), gx1 = min(x0 + 5, W2 - 1);
                const int gy0 = max(y0 - 4, 0), gy1 = min(y0 + 5, W2 - 1);
                if (gx0 > gx1 || gy0 > gy1) continue;
                const int t0 = (lb[l] + gy0 * W2 + gx0) >> 7;
                const int t1 = (lb[l] + gy1 * W2 + gx1) >> 7;
                m |= (((1ULL << (t1 - t0 + 1)) - 1ULL) << t0);
            }
        }
        unsigned lo = (unsigned)m, hi = (unsigned)(m >> 32);
#pragma unroll
        for (int o = 16; o; o >>= 1) {
            lo |= __shfl_xor_sync(0xffffffffu, lo, o);
            hi |= __shfl_xor_sync(0xffffffffu, hi, o);
        }
        if (lane == 0) g_mask[gw] = ((unsigned long long)hi << 32) | lo;
        return;
    }

    const float* src;
    int P, pBase;
    size_t dstOff, bStride;
    if (bx < 128)      { src = f1;  P = 4096; pBase = bx;       dstOff = F1H_OFF;                      bStride = 1048576; }
    else if (bx < 256) { src = f20; P = 4096; pBase = bx - 128; dstOff = F2H_OFF;                      bStride = F2_BSTRIDE; }
    else if (bx < 288) { src = f21; P = 1024; pBase = bx - 256; dstOff = F2H_OFF + (size_t)4096 * 256; bStride = F2_BSTRIDE; }
    else if (bx < 296) { src = f22; P = 256;  pBase = bx - 288; dstOff = F2H_OFF + (size_t)5120 * 256; bStride = F2_BSTRIDE; }
    else               { src = f23; P = 64;   pBase = bx - 296; dstOff = F2H_OFF + (size_t)5376 * 256; bStride = F2_BSTRIDE; }

    const float* s = src + (size_t)bz * 256 * P;
    __half* d = g_fh + dstOff + (size_t)bz * bStride;
    const int p0 = pBase * 32, c0 = blockIdx.y * 32;
#pragma unroll
    for (int k = 0; k < 4; k++)
        tile[ty + 8 * k][tx] = s[(size_t)(c0 + ty + 8 * k) * P + p0 + tx];
    __syncthreads();

    // write: 2 iters; thread -> pixel p = (tid>>4) + 16*it, channel pair c = tid&15
    const int cp = tid & 15, pr = tid >> 4;
#pragma unroll
    for (int it = 0; it < 2; it++) {
        const int p = pr + it * 16;
        const __half2 h = __floats2half2_rn(tile[2 * cp][p], tile[2 * cp + 1][p]);
        *(__half2*)(d + (size_t)(p0 + p) * 256 + c0 + 2 * cp) = h;
    }
}

// ---------------------------------------------------------------------------
// GEMM (round-9 version, exact): 128x128 tile, K=256 in 4 chunks of 64,
// cp.async 3-stage pipeline, 4 warps (2Mx2N, warp tile 64x64),
// 96KB smem -> 2 CTAs/SM.
// ---------------------------------------------------------------------------
#define STAGE_BYTES 32768
#define GEMM_SMEM   (3 * STAGE_BYTES)   // 98304

__device__ __forceinline__ void ldsm_x4(uint32_t (&r)[4], uint32_t addr) {
    asm volatile("ldmatrix.sync.aligned.m8n8.x4.shared.b16 {%0,%1,%2,%3}, [%4];"
                 : "=r"(r[0]), "=r"(r[1]), "=r"(r[2]), "=r"(r[3]) : "r"(addr));
}
__device__ __forceinline__ void mma16816(float (&d)[4], const uint32_t (&a)[4],
                                         uint32_t b0, uint32_t b1) {
    asm volatile(
        "mma.sync.aligned.m16n8k16.row.col.f32.f16.f16.f32 "
        "{%0,%1,%2,%3},{%4,%5,%6,%7},{%8,%9},{%0,%1,%2,%3};"
        : "+f"(d[0]), "+f"(d[1]), "+f"(d[2]), "+f"(d[3])
        : "r"(a[0]), "r"(a[1]), "r"(a[2]), "r"(a[3]), "r"(b0), "r"(b1));
}

__device__ __forceinline__ uint32_t sw_addr(uint32_t base, int row, int chunk) {
    return base + (uint32_t)row * 128u + (uint32_t)((chunk ^ (row & 7)) << 4);
}

__device__ __forceinline__ void load_chunk(const __half* __restrict__ A,
                                           const __half* __restrict__ B,
                                           uint32_t sbase, int stage, int ck, int tid) {
    const uint32_t aoff = sbase + stage * STAGE_BYTES;
    const uint32_t boff = aoff + 16384;
#pragma unroll
    for (int q = tid; q < 1024; q += 128) {
        const int r = q >> 3, c = q & 7;
        const uint32_t sa = sw_addr(aoff, r, c);
        const uint32_t sb = sw_addr(boff, r, c);
        const __half* ga = A + (size_t)r * 256 + ck * 64 + c * 8;
        const __half* gb = B + (size_t)r * 256 + ck * 64 + c * 8;
        asm volatile("cp.async.cg.shared.global [%0], [%1], 16;" :: "r"(sa), "l"(ga));
        asm volatile("cp.async.cg.shared.global [%0], [%1], 16;" :: "r"(sb), "l"(gb));
    }
    asm volatile("cp.async.commit_group;" ::: "memory");
}

__global__ void __launch_bounds__(128, 2) gemm_kernel() {
    const int nt = blockIdx.x, mt = blockIdx.y, b = blockIdx.z;
    if (!((g_mask[b * 32 + mt] >> nt) & 1ULL)) return;

    extern __shared__ char smraw[];
    const uint32_t sbase = smem_u32(smraw);
    const int tid = threadIdx.x, warp = tid >> 5, lane = tid & 31;

    const __half* A = g_fh + F1H_OFF + ((size_t)b * 4096 + (size_t)mt * 128) * 256;
    const __half* B = g_fh + F2H_OFF + (size_t)b * F2_BSTRIDE + (size_t)nt * 128 * 256;

    load_chunk(A, B, sbase, 0, 0, tid);
    load_chunk(A, B, sbase, 1, 1, tid);

    const int wm = (warp & 1) * 64;
    const int wn = (warp >> 1) * 64;
    const int row_in = lane & 7;
    const int mat = lane >> 3;

    float acc[4][8][4];
#pragma unroll
    for (int mi = 0; mi < 4; mi++)
#pragma unroll
        for (int ni = 0; ni < 8; ni++)
#pragma unroll
            for (int j = 0; j < 4; j++) acc[mi][ni][j] = 0.0f;

#pragma unroll
    for (int ck = 0; ck < 4; ck++) {
        if (ck < 3) asm volatile("cp.async.wait_group 1;" ::: "memory");
        else        asm volatile("cp.async.wait_group 0;" ::: "memory");
        __syncthreads();
        if (ck + 2 < 4) load_chunk(A, B, sbase, (ck + 2) % 3, ck + 2, tid);

        const uint32_t aT = sbase + (ck % 3) * STAGE_BYTES;
        const uint32_t bT = aT + 16384;

#pragma unroll
        for (int ks = 0; ks < 4; ks++) {
            uint32_t af[4][4];
#pragma unroll
            for (int mi = 0; mi < 4; mi++) {
                const int row = wm + mi * 16 + (mat & 1) * 8 + row_in;
                ldsm_x4(af[mi], sw_addr(aT, row, ks * 2 + (mat >> 1)));
            }
            uint32_t bf[4][4];
#pragma unroll
            for (int bi = 0; bi < 4; bi++) {
                const int nrow = wn + bi * 16 + (mat >> 1) * 8 + row_in;
                ldsm_x4(bf[bi], sw_addr(bT, nrow, ks * 2 + (mat & 1)));
            }
#pragma unroll
            for (int mi = 0; mi < 4; mi++)
#pragma unroll
                for (int ni = 0; ni < 8; ni++) {
                    const uint32_t* bb = bf[ni >> 1];
                    if (ni & 1) mma16816(acc[mi][ni], af[mi], bb[2], bb[3]);
                    else        mma16816(acc[mi][ni], af[mi], bb[0], bb[1]);
                }
        }
    }

    const int g = lane >> 2, tg = lane & 3;
    __half* crow = g_corrh + ((size_t)b * 4096 + (size_t)mt * 128) * CORR_COLS +
                   (size_t)nt * 128;
#pragma unroll
    for (int mi = 0; mi < 4; mi++) {
#pragma unroll
        for (int ni = 0; ni < 8; ni++) {
            const int rm = wm + mi * 16 + g;
            const int cn = wn + ni * 8 + tg * 2;
            *(__half2*)(crow + (size_t)rm * CORR_COLS + cn) =
                __floats2half2_rn(acc[mi][ni][0], acc[mi][ni][1]);
            *(__half2*)(crow + (size_t)(rm + 8) * CORR_COLS + cn) =
                __floats2half2_rn(acc[mi][ni][2], acc[mi][ni][3]);
        }
    }
}

// ---------------------------------------------------------------------------
// Gather v2 (round-9 version, exact).
// ---------------------------------------------------------------------------
__global__ __launch_bounds__(256) void gather_kernel(const float* __restrict__ coords,
                                                     float* __restrict__ out) {
    __shared__ float dots[4][8][104];
    __shared__ float s_cx[8], s_cy[8];

    const int tid = threadIdx.x;
    const int pix0 = blockIdx.x * 8;
    const int b = pix0 >> 12;
    const int hw = pix0 & 4095;

    if (tid < 8) {
        s_cx[tid] = coords[(size_t)b * 8192 + hw + tid];
        s_cy[tid] = coords[(size_t)b * 8192 + 4096 + hw + tid];
    }
    __syncthreads();

    const int lvl_base[4] = {0, 4096, 5120, 5376};

#pragma unroll
    for (int it = 0; it < 16; it++) {
        const int e = tid + it * 256;           // e < 4096
        const int pt = e & 127;
        const int px = (e >> 7) & 7;
        const int lvl = e >> 10;
        if (pt < 100) {
            const int W2 = 64 >> lvl;
            const float scale = 1.0f / (float)(1 << lvl);
            const float x = s_cx[px] * scale;
            const float y = s_cy[px] * scale;
            const int x0 = (int)floorf(x);
            const int y0 = (int)floorf(y);
            const int gi = pt / 10;
            const int gj = pt - gi * 10;
            const int gx = x0 - 4 + gj;
            const int gy = y0 - 4 + gi;
            float v = 0.0f;
            if ((unsigned)gx < (unsigned)W2 && (unsigned)gy < (unsigned)W2)
                v = __half2float(g_corrh[((size_t)b * 4096 + hw + px) * CORR_COLS +
                                         lvl_base[lvl] + gy * W2 + gx]);
            dots[lvl][px][pt] = v;
        }
    }
    __syncthreads();

#pragma unroll
    for (int it = 0; it < 11; it++) {
        const int e = tid + it * 256;
        if (e < 2592) {
            const int lvl = e / 648;
            const int r = e - lvl * 648;
            const int k = r >> 3;
            const int px = r & 7;
            const int oi = k / 9;
            const int oj = k - oi * 9;
            const float scale = 1.0f / (float)(1 << lvl);
            const float x = s_cx[px] * scale;
            const float y = s_cy[px] * scale;
            const float fx = x - floorf(x);
            const float fy = y - floorf(y);
            const float w00 = (1.0f - fx) * (1.0f - fy);
            const float w10 = fx * (1.0f - fy);
            const float w01 = (1.0f - fx) * fy;
            const float w11 = fx * fy;
            const int base = oi * 10 + oj;
            const float* dp = dots[lvl][px];
            const float val = w00 * dp[base]      + w10 * dp[base + 1] +
                              w01 * dp[base + 10] + w11 * dp[base + 11];
            out[(size_t)(b * 324 + lvl * 81 + k) * 4096 + hw + px] = val * 0.0625f;
        }
    }
}

// ---------------------------------------------------------------------------
// Inputs: fmap1, fmap2_0..3, coords. Output [2,324,64,64] fp32.
// ---------------------------------------------------------------------------
extern "C" void kernel_launch(void* const* d_in, const int* in_sizes, int n_in,
                              void* d_out, int out_size) {
    const float* f1 = (const float*)d_in[0];
    const float* f2_0 = (const float*)d_in[1];
    const float* f2_1 = (const float*)d_in[2];
    const float* f2_2 = (const float*)d_in[3];
    const float* f2_3 = (const float*)d_in[4];
    const float* coords = (const float*)d_in[5];
    float* out = (float*)d_out;

    static bool attr_done = false;
    if (!attr_done) {
        cudaFuncSetAttribute(gemm_kernel, cudaFuncAttributeMaxDynamicSharedMemorySize,
                             GEMM_SMEM);
        attr_done = true;
    }

    tconv_kernel<<<dim3(306, 8, 2), 256>>>(f1, f2_0, f2_1, f2_2, f2_3, coords);
    gemm_kernel<<<dim3(43, 32, 2), 128, GEMM_SMEM>>>();
    gather_kernel<<<1024, 256>>>(coords, out);
}

// round 13
// speedup vs baseline: 1.3308x; 1.0081x over previous
#include <cuda_runtime.h>
#include <cuda_fp16.h>
#include <cstdint>
#include <cstddef>

// ---------------------------------------------------------------------------
// Scratch:
//   g_fh: f1h [2][4096][256] fp16 at 0; f2h [2][5504][256] fp16 at 2,097,152
//         (f2 level row bases 0,4096,5120,5376; rows 5440..5503 stay zero)
//   g_corrh: [2][4096][5504] fp16 correlation volume
//   g_mask: per (b, m-tile) bitmask of needed n-tiles (43 bits used)
// ---------------------------------------------------------------------------
#define F1H_OFF ((size_t)0)
#define F2H_OFF ((size_t)2097152)
#define F2_BSTRIDE ((size_t)1409024)   // 5504*256
#define CORR_COLS 5504
__device__ __half g_fh[4915200];
__device__ __half g_corrh[45088768];
__device__ unsigned long long g_mask[64];

__device__ __forceinline__ uint32_t smem_u32(const void* p) {
    uint32_t a;
    asm("{ .reg .u64 t; cvta.to.shared.u64 t, %1; cvt.u32.u64 %0, t; }"
        : "=r"(a) : "l"(p));
    return a;
}

// ---------------------------------------------------------------------------
// tconv v3: per 32px x 32ch tile: 1 LDG.128 + 4 STS.32 + 4 LDS.32 + 1 STG.64
// per thread; both smem phases bank-conflict-free. Mask warps unchanged.
// ---------------------------------------------------------------------------
__global__ __launch_bounds__(256) void tconv_kernel(
    const float* __restrict__ f1, const float* __restrict__ f20,
    const float* __restrict__ f21, const float* __restrict__ f22,
    const float* __restrict__ f23, const float* __restrict__ coords) {
    __shared__ float tile[32][33];
    const int bx = blockIdx.x, bz = blockIdx.z;
    const int tid = threadIdx.x;

    if (bx >= 298) {
        if (blockIdx.y != 0 || bz != 0) return;
        const int gw = (bx - 298) * 8 + (tid >> 5);   // 0..63
        const int lane = tid & 31;
        const int b = gw >> 5, mt = gw & 31;
        const int lb[4] = {0, 4096, 5120, 5376};
        unsigned long long m = 0ULL;
#pragma unroll
        for (int j = 0; j < 4; j++) {
            const int hw = mt * 128 + j * 32 + lane;
            const float x = coords[(size_t)b * 8192 + hw];
            const float y = coords[(size_t)b * 8192 + 4096 + hw];
#pragma unroll
            for (int l = 0; l < 4; l++) {
                const int W2 = 64 >> l;
                const float s = 1.0f / (float)(1 << l);
                const int x0 = (int)floorf(x * s);
                const int y0 = (int)floorf(y * s);
                const int gx0 = max(x0 - 4, 0), gx1 = min(x0 + 5, W2 - 1);
                const int gy0 = max(y0 - 4, 0), gy1 = min(y0 + 5, W2 - 1);
                if (gx0 > gx1 || gy0 > gy1) continue;
                const int t0 = (lb[l] + gy0 * W2 + gx0) >> 7;
                const int t1 = (lb[l] + gy1 * W2 + gx1) >> 7;
                m |= (((1ULL << (t1 - t0 + 1)) - 1ULL) << t0);
            }
        }
        unsigned lo = (unsigned)m, hi = (unsigned)(m >> 32);
#pragma unroll
        for (int o = 16; o; o >>= 1) {
            lo |= __shfl_xor_sync(0xffffffffu, lo, o);
            hi |= __shfl_xor_sync(0xffffffffu, hi, o);
        }
        if (lane == 0) g_mask[gw] = ((unsigned long long)hi << 32) | lo;
        return;
    }

    const float* src;
    int P, pBase;
    size_t dstOff, bStride;
    if (bx < 128)      { src = f1;  P = 4096; pBase = bx;       dstOff = F1H_OFF;                      bStride = 1048576; }
    else if (bx < 256) { src = f20; P = 4096; pBase = bx - 128; dstOff = F2H_OFF;                      bStride = F2_BSTRIDE; }
    else if (bx < 288) { src = f21; P = 1024; pBase = bx - 256; dstOff = F2H_OFF + (size_t)4096 * 256; bStride = F2_BSTRIDE; }
    else if (bx < 296) { src = f22; P = 256;  pBase = bx - 288; dstOff = F2H_OFF + (size_t)5120 * 256; bStride = F2_BSTRIDE; }
    else               { src = f23; P = 64;   pBase = bx - 296; dstOff = F2H_OFF + (size_t)5376 * 256; bStride = F2_BSTRIDE; }

    const float* s = src + (size_t)bz * 256 * P;
    __half* d = g_fh + dstOff + (size_t)bz * bStride;
    const int p0 = pBase * 32, c0 = blockIdx.y * 32;

    // Load: thread t -> channel row c = t>>3, pixels p4 = (t&7)*4 .. +3 (float4).
    {
        const int c = tid >> 3, p4 = (tid & 7) * 4;
        const float4 v = *(const float4*)(s + (size_t)(c0 + c) * P + p0 + p4);
        tile[c][p4] = v.x; tile[c][p4 + 1] = v.y;
        tile[c][p4 + 2] = v.z; tile[c][p4 + 3] = v.w;
    }
    __syncthreads();

    // Store: warp w, lane l -> pixel px = 4w + (l>>3), channel quad cq = l&7.
    {
        const int w = tid >> 5, l = tid & 31;
        const int px = 4 * w + (l >> 3), cq = l & 7;
        const __half2 h0 = __floats2half2_rn(tile[4 * cq][px],     tile[4 * cq + 1][px]);
        const __half2 h1 = __floats2half2_rn(tile[4 * cq + 2][px], tile[4 * cq + 3][px]);
        uint2 u;
        u.x = *(const uint32_t*)&h0;
        u.y = *(const uint32_t*)&h1;
        *(uint2*)(d + (size_t)(p0 + px) * 256 + c0 + 4 * cq) = u;
    }
}

// ---------------------------------------------------------------------------
// GEMM (round-9 version, exact): 128x128 tile, K=256 in 4 chunks of 64,
// cp.async 3-stage pipeline, 4 warps (2Mx2N, warp tile 64x64),
// 96KB smem -> 2 CTAs/SM.
// ---------------------------------------------------------------------------
#define STAGE_BYTES 32768
#define GEMM_SMEM   (3 * STAGE_BYTES)   // 98304

__device__ __forceinline__ void ldsm_x4(uint32_t (&r)[4], uint32_t addr) {
    asm volatile("ldmatrix.sync.aligned.m8n8.x4.shared.b16 {%0,%1,%2,%3}, [%4];"
                 : "=r"(r[0]), "=r"(r[1]), "=r"(r[2]), "=r"(r[3]) : "r"(addr));
}
__device__ __forceinline__ void mma16816(float (&d)[4], const uint32_t (&a)[4],
                                         uint32_t b0, uint32_t b1) {
    asm volatile(
        "mma.sync.aligned.m16n8k16.row.col.f32.f16.f16.f32 "
        "{%0,%1,%2,%3},{%4,%5,%6,%7},{%8,%9},{%0,%1,%2,%3};"
        : "+f"(d[0]), "+f"(d[1]), "+f"(d[2]), "+f"(d[3])
        : "r"(a[0]), "r"(a[1]), "r"(a[2]), "r"(a[3]), "r"(b0), "r"(b1));
}

__device__ __forceinline__ uint32_t sw_addr(uint32_t base, int row, int chunk) {
    return base + (uint32_t)row * 128u + (uint32_t)((chunk ^ (row & 7)) << 4);
}

__device__ __forceinline__ void load_chunk(const __half* __restrict__ A,
                                           const __half* __restrict__ B,
                                           uint32_t sbase, int stage, int ck, int tid) {
    const uint32_t aoff = sbase + stage * STAGE_BYTES;
    const uint32_t boff = aoff + 16384;
#pragma unroll
    for (int q = tid; q < 1024; q += 128) {
        const int r = q >> 3, c = q & 7;
        const uint32_t sa = sw_addr(aoff, r, c);
        const uint32_t sb = sw_addr(boff, r, c);
        const __half* ga = A + (size_t)r * 256 + ck * 64 + c * 8;
        const __half* gb = B + (size_t)r * 256 + ck * 64 + c * 8;
        asm volatile("cp.async.cg.shared.global [%0], [%1], 16;" :: "r"(sa), "l"(ga));
        asm volatile("cp.async.cg.shared.global [%0], [%1], 16;" :: "r"(sb), "l"(gb));
    }
    asm volatile("cp.async.commit_group;" ::: "memory");
}

__global__ void __launch_bounds__(128, 2) gemm_kernel() {
    const int nt = blockIdx.x, mt = blockIdx.y, b = blockIdx.z;
    if (!((g_mask[b * 32 + mt] >> nt) & 1ULL)) return;

    extern __shared__ char smraw[];
    const uint32_t sbase = smem_u32(smraw);
    const int tid = threadIdx.x, warp = tid >> 5, lane = tid & 31;

    const __half* A = g_fh + F1H_OFF + ((size_t)b * 4096 + (size_t)mt * 128) * 256;
    const __half* B = g_fh + F2H_OFF + (size_t)b * F2_BSTRIDE + (size_t)nt * 128 * 256;

    load_chunk(A, B, sbase, 0, 0, tid);
    load_chunk(A, B, sbase, 1, 1, tid);

    const int wm = (warp & 1) * 64;
    const int wn = (warp >> 1) * 64;
    const int row_in = lane & 7;
    const int mat = lane >> 3;

    float acc[4][8][4];
#pragma unroll
    for (int mi = 0; mi < 4; mi++)
#pragma unroll
        for (int ni = 0; ni < 8; ni++)
#pragma unroll
            for (int j = 0; j < 4; j++) acc[mi][ni][j] = 0.0f;

#pragma unroll
    for (int ck = 0; ck < 4; ck++) {
        if (ck < 3) asm volatile("cp.async.wait_group 1;" ::: "memory");
        else        asm volatile("cp.async.wait_group 0;" ::: "memory");
        __syncthreads();
        if (ck + 2 < 4) load_chunk(A, B, sbase, (ck + 2) % 3, ck + 2, tid);

        const uint32_t aT = sbase + (ck % 3) * STAGE_BYTES;
        const uint32_t bT = aT + 16384;

#pragma unroll
        for (int ks = 0; ks < 4; ks++) {
            uint32_t af[4][4];
#pragma unroll
            for (int mi = 0; mi < 4; mi++) {
                const int row = wm + mi * 16 + (mat & 1) * 8 + row_in;
                ldsm_x4(af[mi], sw_addr(aT, row, ks * 2 + (mat >> 1)));
            }
            uint32_t bf[4][4];
#pragma unroll
            for (int bi = 0; bi < 4; bi++) {
                const int nrow = wn + bi * 16 + (mat >> 1) * 8 + row_in;
                ldsm_x4(bf[bi], sw_addr(bT, nrow, ks * 2 + (mat & 1)));
            }
#pragma unroll
            for (int mi = 0; mi < 4; mi++)
#pragma unroll
                for (int ni = 0; ni < 8; ni++) {
                    const uint32_t* bb = bf[ni >> 1];
                    if (ni & 1) mma16816(acc[mi][ni], af[mi], bb[2], bb[3]);
                    else        mma16816(acc[mi][ni], af[mi], bb[0], bb[1]);
                }
        }
    }

    const int g = lane >> 2, tg = lane & 3;
    __half* crow = g_corrh + ((size_t)b * 4096 + (size_t)mt * 128) * CORR_COLS +
                   (size_t)nt * 128;
#pragma unroll
    for (int mi = 0; mi < 4; mi++) {
#pragma unroll
        for (int ni = 0; ni < 8; ni++) {
            const int rm = wm + mi * 16 + g;
            const int cn = wn + ni * 8 + tg * 2;
            *(__half2*)(crow + (size_t)rm * CORR_COLS + cn) =
                __floats2half2_rn(acc[mi][ni][0], acc[mi][ni][1]);
            *(__half2*)(crow + (size_t)(rm + 8) * CORR_COLS + cn) =
                __floats2half2_rn(acc[mi][ni][2], acc[mi][ni][3]);
        }
    }
}

// ---------------------------------------------------------------------------
// Gather v2 (round-9 version, exact).
// ---------------------------------------------------------------------------
__global__ __launch_bounds__(256) void gather_kernel(const float* __restrict__ coords,
                                                     float* __restrict__ out) {
    __shared__ float dots[4][8][104];
    __shared__ float s_cx[8], s_cy[8];

    const int tid = threadIdx.x;
    const int pix0 = blockIdx.x * 8;
    const int b = pix0 >> 12;
    const int hw = pix0 & 4095;

    if (tid < 8) {
        s_cx[tid] = coords[(size_t)b * 8192 + hw + tid];
        s_cy[tid] = coords[(size_t)b * 8192 + 4096 + hw + tid];
    }
    __syncthreads();

    const int lvl_base[4] = {0, 4096, 5120, 5376};

#pragma unroll
    for (int it = 0; it < 16; it++) {
        const int e = tid + it * 256;           // e < 4096
        const int pt = e & 127;
        const int px = (e >> 7) & 7;
        const int lvl = e >> 10;
        if (pt < 100) {
            const int W2 = 64 >> lvl;
            const float scale = 1.0f / (float)(1 << lvl);
            const float x = s_cx[px] * scale;
            const float y = s_cy[px] * scale;
            const int x0 = (int)floorf(x);
            const int y0 = (int)floorf(y);
            const int gi = pt / 10;
            const int gj = pt - gi * 10;
            const int gx = x0 - 4 + gj;
            const int gy = y0 - 4 + gi;
            float v = 0.0f;
            if ((unsigned)gx < (unsigned)W2 && (unsigned)gy < (unsigned)W2)
                v = __half2float(g_corrh[((size_t)b * 4096 + hw + px) * CORR_COLS +
                                         lvl_base[lvl] + gy * W2 + gx]);
            dots[lvl][px][pt] = v;
        }
    }
    __syncthreads();

#pragma unroll
    for (int it = 0; it < 11; it++) {
        const int e = tid + it * 256;
        if (e < 2592) {
            const int lvl = e / 648;
            const int r = e - lvl * 648;
            const int k = r >> 3;
            const int px = r & 7;
            const int oi = k / 9;
            const int oj = k - oi * 9;
            const float scale = 1.0f / (float)(1 << lvl);
            const float x = s_cx[px] * scale;
            const float y = s_cy[px] * scale;
            const float fx = x - floorf(x);
            const float fy = y - floorf(y);
            const float w00 = (1.0f - fx) * (1.0f - fy);
            const float w10 = fx * (1.0f - fy);
            const float w01 = (1.0f - fx) * fy;
            const float w11 = fx * fy;
            const int base = oi * 10 + oj;
            const float* dp = dots[lvl][px];
            const float val = w00 * dp[base]      + w10 * dp[base + 1] +
                              w01 * dp[base + 10] + w11 * dp[base + 11];
            out[(size_t)(b * 324 + lvl * 81 + k) * 4096 + hw + px] = val * 0.0625f;
        }
    }
}

// ---------------------------------------------------------------------------
// Inputs: fmap1, fmap2_0..3, coords. Output [2,324,64,64] fp32.
// ---------------------------------------------------------------------------
extern "C" void kernel_launch(void* const* d_in, const int* in_sizes, int n_in,
                              void* d_out, int out_size) {
    const float* f1 = (const float*)d_in[0];
    const float* f2_0 = (const float*)d_in[1];
    const float* f2_1 = (const float*)d_in[2];
    const float* f2_2 = (const float*)d_in[3];
    const float* f2_3 = (const float*)d_in[4];
    const float* coords = (const float*)d_in[5];
    float* out = (float*)d_out;

    static bool attr_done = false;
    if (!attr_done) {
        cudaFuncSetAttribute(gemm_kernel, cudaFuncAttributeMaxDynamicSharedMemorySize,
                             GEMM_SMEM);
        attr_done = true;
    }

    tconv_kernel<<<dim3(306, 8, 2), 256>>>(f1, f2_0, f2_1, f2_2, f2_3, coords);
    gemm_kernel<<<dim3(43, 32, 2), 128, GEMM_SMEM>>>();
    gather_kernel<<<1024, 256>>>(coords, out);
}

// round 14
// speedup vs baseline: 1.3519x; 1.0159x over previous
#include <cuda_runtime.h>
#include <cuda_fp16.h>
#include <cstdint>
#include <cstddef>

// ---------------------------------------------------------------------------
// Scratch:
//   g_fh: f1h [2][4096][256] fp16 at 0; f2h [2][5504][256] fp16 at 2,097,152
//         (f2 level row bases 0,4096,5120,5376; rows 5440..5503 stay zero)
//   g_corrh: [2][4096][5504] fp16 correlation volume
//   g_mask: per (b, m-tile) bitmask of needed n-tiles (43 bits used)
// ---------------------------------------------------------------------------
#define F1H_OFF ((size_t)0)
#define F2H_OFF ((size_t)2097152)
#define F2_BSTRIDE ((size_t)1409024)   // 5504*256
#define CORR_COLS 5504
__device__ __half g_fh[4915200];
__device__ __half g_corrh[45088768];
__device__ unsigned long long g_mask[64];

__device__ __forceinline__ uint32_t smem_u32(const void* p) {
    uint32_t a;
    asm("{ .reg .u64 t; cvta.to.shared.u64 t, %1; cvt.u32.u64 %0, t; }"
        : "=r"(a) : "l"(p));
    return a;
}

// ---------------------------------------------------------------------------
// tconv v4: 32px x 128ch slab per block. 4 independent LDG.128 (MLP=4) into
// 4 smem tiles, one sync, 4 store iterations (STG.64). Both smem phases
// bank-conflict-free (same layout math as v3). Mask warps unchanged.
// grid: (306, 2, 2); bx>=298 & by==0 & bz==0 -> mask warps.
// ---------------------------------------------------------------------------
__global__ __launch_bounds__(256) void tconv_kernel(
    const float* __restrict__ f1, const float* __restrict__ f20,
    const float* __restrict__ f21, const float* __restrict__ f22,
    const float* __restrict__ f23, const float* __restrict__ coords) {
    __shared__ float tile[4][32][33];
    const int bx = blockIdx.x, bz = blockIdx.z;
    const int tid = threadIdx.x;

    if (bx >= 298) {
        if (blockIdx.y != 0 || bz != 0) return;
        const int gw = (bx - 298) * 8 + (tid >> 5);   // 0..63
        const int lane = tid & 31;
        const int b = gw >> 5, mt = gw & 31;
        const int lb[4] = {0, 4096, 5120, 5376};
        unsigned long long m = 0ULL;
#pragma unroll
        for (int j = 0; j < 4; j++) {
            const int hw = mt * 128 + j * 32 + lane;
            const float x = coords[(size_t)b * 8192 + hw];
            const float y = coords[(size_t)b * 8192 + 4096 + hw];
#pragma unroll
            for (int l = 0; l < 4; l++) {
                const int W2 = 64 >> l;
                const float s = 1.0f / (float)(1 << l);
                const int x0 = (int)floorf(x * s);
                const int y0 = (int)floorf(y * s);
                const int gx0 = max(x0 - 4, 0), gx1 = min(x0 + 5, W2 - 1);
                const int gy0 = max(y0 - 4, 0), gy1 = min(y0 + 5, W2 - 1);
                if (gx0 > gx1 || gy0 > gy1) continue;
                const int t0 = (lb[l] + gy0 * W2 + gx0) >> 7;
                const int t1 = (lb[l] + gy1 * W2 + gx1) >> 7;
                m |= (((1ULL << (t1 - t0 + 1)) - 1ULL) << t0);
            }
        }
        unsigned lo = (unsigned)m, hi = (unsigned)(m >> 32);
#pragma unroll
        for (int o = 16; o; o >>= 1) {
            lo |= __shfl_xor_sync(0xffffffffu, lo, o);
            hi |= __shfl_xor_sync(0xffffffffu, hi, o);
        }
        if (lane == 0) g_mask[gw] = ((unsigned long long)hi << 32) | lo;
        return;
    }

    const float* src;
    int P, pBase;
    size_t dstOff, bStride;
    if (bx < 128)      { src = f1;  P = 4096; pBase = bx;       dstOff = F1H_OFF;                      bStride = 1048576; }
    else if (bx < 256) { src = f20; P = 4096; pBase = bx - 128; dstOff = F2H_OFF;                      bStride = F2_BSTRIDE; }
    else if (bx < 288) { src = f21; P = 1024; pBase = bx - 256; dstOff = F2H_OFF + (size_t)4096 * 256; bStride = F2_BSTRIDE; }
    else if (bx < 296) { src = f22; P = 256;  pBase = bx - 288; dstOff = F2H_OFF + (size_t)5120 * 256; bStride = F2_BSTRIDE; }
    else               { src = f23; P = 64;   pBase = bx - 296; dstOff = F2H_OFF + (size_t)5376 * 256; bStride = F2_BSTRIDE; }

    const float* s = src + (size_t)bz * 256 * P;
    __half* d = g_fh + dstOff + (size_t)bz * bStride;
    const int p0 = pBase * 32, c0 = blockIdx.y * 128;

    // Load: 4 independent k-slabs; thread t -> channel c = k*32 + (t>>3),
    // pixels p4 = (t&7)*4 (float4). MLP = 4.
    {
        const int cr = tid >> 3, p4 = (tid & 7) * 4;
        float4 v[4];
#pragma unroll
        for (int k = 0; k < 4; k++)
            v[k] = *(const float4*)(s + (size_t)(c0 + k * 32 + cr) * P + p0 + p4);
#pragma unroll
        for (int k = 0; k < 4; k++) {
            tile[k][cr][p4] = v[k].x; tile[k][cr][p4 + 1] = v[k].y;
            tile[k][cr][p4 + 2] = v[k].z; tile[k][cr][p4 + 3] = v[k].w;
        }
    }
    __syncthreads();

    // Store: warp w, lane l -> pixel px = 4w + (l>>3), channel quad cq = l&7,
    // 4 iterations over the k-slabs (STG.64 each).
    {
        const int w = tid >> 5, l = tid & 31;
        const int px = 4 * w + (l >> 3), cq = l & 7;
        __half* drow = d + (size_t)(p0 + px) * 256 + c0 + 4 * cq;
#pragma unroll
        for (int k = 0; k < 4; k++) {
            const __half2 h0 = __floats2half2_rn(tile[k][4 * cq][px],     tile[k][4 * cq + 1][px]);
            const __half2 h1 = __floats2half2_rn(tile[k][4 * cq + 2][px], tile[k][4 * cq + 3][px]);
            uint2 u;
            u.x = *(const uint32_t*)&h0;
            u.y = *(const uint32_t*)&h1;
            *(uint2*)(drow + k * 32) = u;
        }
    }
}

// ---------------------------------------------------------------------------
// GEMM (round-9 version, exact): 128x128 tile, K=256 in 4 chunks of 64,
// cp.async 3-stage pipeline, 4 warps (2Mx2N, warp tile 64x64),
// 96KB smem -> 2 CTAs/SM.
// ---------------------------------------------------------------------------
#define STAGE_BYTES 32768
#define GEMM_SMEM   (3 * STAGE_BYTES)   // 98304

__device__ __forceinline__ void ldsm_x4(uint32_t (&r)[4], uint32_t addr) {
    asm volatile("ldmatrix.sync.aligned.m8n8.x4.shared.b16 {%0,%1,%2,%3}, [%4];"
                 : "=r"(r[0]), "=r"(r[1]), "=r"(r[2]), "=r"(r[3]) : "r"(addr));
}
__device__ __forceinline__ void mma16816(float (&d)[4], const uint32_t (&a)[4],
                                         uint32_t b0, uint32_t b1) {
    asm volatile(
        "mma.sync.aligned.m16n8k16.row.col.f32.f16.f16.f32 "
        "{%0,%1,%2,%3},{%4,%5,%6,%7},{%8,%9},{%0,%1,%2,%3};"
        : "+f"(d[0]), "+f"(d[1]), "+f"(d[2]), "+f"(d[3])
        : "r"(a[0]), "r"(a[1]), "r"(a[2]), "r"(a[3]), "r"(b0), "r"(b1));
}

__device__ __forceinline__ uint32_t sw_addr(uint32_t base, int row, int chunk) {
    return base + (uint32_t)row * 128u + (uint32_t)((chunk ^ (row & 7)) << 4);
}

__device__ __forceinline__ void load_chunk(const __half* __restrict__ A,
                                           const __half* __restrict__ B,
                                           uint32_t sbase, int stage, int ck, int tid) {
    const uint32_t aoff = sbase + stage * STAGE_BYTES;
    const uint32_t boff = aoff + 16384;
#pragma unroll
    for (int q = tid; q < 1024; q += 128) {
        const int r = q >> 3, c = q & 7;
        const uint32_t sa = sw_addr(aoff, r, c);
        const uint32_t sb = sw_addr(boff, r, c);
        const __half* ga = A + (size_t)r * 256 + ck * 64 + c * 8;
        const __half* gb = B + (size_t)r * 256 + ck * 64 + c * 8;
        asm volatile("cp.async.cg.shared.global [%0], [%1], 16;" :: "r"(sa), "l"(ga));
        asm volatile("cp.async.cg.shared.global [%0], [%1], 16;" :: "r"(sb), "l"(gb));
    }
    asm volatile("cp.async.commit_group;" ::: "memory");
}

__global__ void __launch_bounds__(128, 2) gemm_kernel() {
    const int nt = blockIdx.x, mt = blockIdx.y, b = blockIdx.z;
    if (!((g_mask[b * 32 + mt] >> nt) & 1ULL)) return;

    extern __shared__ char smraw[];
    const uint32_t sbase = smem_u32(smraw);
    const int tid = threadIdx.x, warp = tid >> 5, lane = tid & 31;

    const __half* A = g_fh + F1H_OFF + ((size_t)b * 4096 + (size_t)mt * 128) * 256;
    const __half* B = g_fh + F2H_OFF + (size_t)b * F2_BSTRIDE + (size_t)nt * 128 * 256;

    load_chunk(A, B, sbase, 0, 0, tid);
    load_chunk(A, B, sbase, 1, 1, tid);

    const int wm = (warp & 1) * 64;
    const int wn = (warp >> 1) * 64;
    const int row_in = lane & 7;
    const int mat = lane >> 3;

    float acc[4][8][4];
#pragma unroll
    for (int mi = 0; mi < 4; mi++)
#pragma unroll
        for (int ni = 0; ni < 8; ni++)
#pragma unroll
            for (int j = 0; j < 4; j++) acc[mi][ni][j] = 0.0f;

#pragma unroll
    for (int ck = 0; ck < 4; ck++) {
        if (ck < 3) asm volatile("cp.async.wait_group 1;" ::: "memory");
        else        asm volatile("cp.async.wait_group 0;" ::: "memory");
        __syncthreads();
        if (ck + 2 < 4) load_chunk(A, B, sbase, (ck + 2) % 3, ck + 2, tid);

        const uint32_t aT = sbase + (ck % 3) * STAGE_BYTES;
        const uint32_t bT = aT + 16384;

#pragma unroll
        for (int ks = 0; ks < 4; ks++) {
            uint32_t af[4][4];
#pragma unroll
            for (int mi = 0; mi < 4; mi++) {
                const int row = wm + mi * 16 + (mat & 1) * 8 + row_in;
                ldsm_x4(af[mi], sw_addr(aT, row, ks * 2 + (mat >> 1)));
            }
            uint32_t bf[4][4];
#pragma unroll
            for (int bi = 0; bi < 4; bi++) {
                const int nrow = wn + bi * 16 + (mat >> 1) * 8 + row_in;
                ldsm_x4(bf[bi], sw_addr(bT, nrow, ks * 2 + (mat & 1)));
            }
#pragma unroll
            for (int mi = 0; mi < 4; mi++)
#pragma unroll
                for (int ni = 0; ni < 8; ni++) {
                    const uint32_t* bb = bf[ni >> 1];
                    if (ni & 1) mma16816(acc[mi][ni], af[mi], bb[2], bb[3]);
                    else        mma16816(acc[mi][ni], af[mi], bb[0], bb[1]);
                }
        }
    }

    const int g = lane >> 2, tg = lane & 3;
    __half* crow = g_corrh + ((size_t)b * 4096 + (size_t)mt * 128) * CORR_COLS +
                   (size_t)nt * 128;
#pragma unroll
    for (int mi = 0; mi < 4; mi++) {
#pragma unroll
        for (int ni = 0; ni < 8; ni++) {
            const int rm = wm + mi * 16 + g;
            const int cn = wn + ni * 8 + tg * 2;
            *(__half2*)(crow + (size_t)rm * CORR_COLS + cn) =
                __floats2half2_rn(acc[mi][ni][0], acc[mi][ni][1]);
            *(__half2*)(crow + (size_t)(rm + 8) * CORR_COLS + cn) =
                __floats2half2_rn(acc[mi][ni][2], acc[mi][ni][3]);
        }
    }
}

// ---------------------------------------------------------------------------
// Gather v2 (round-9 version, exact).
// ---------------------------------------------------------------------------
__global__ __launch_bounds__(256) void gather_kernel(const float* __restrict__ coords,
                                                     float* __restrict__ out) {
    __shared__ float dots[4][8][104];
    __shared__ float s_cx[8], s_cy[8];

    const int tid = threadIdx.x;
    const int pix0 = blockIdx.x * 8;
    const int b = pix0 >> 12;
    const int hw = pix0 & 4095;

    if (tid < 8) {
        s_cx[tid] = coords[(size_t)b * 8192 + hw + tid];
        s_cy[tid] = coords[(size_t)b * 8192 + 4096 + hw + tid];
    }
    __syncthreads();

    const int lvl_base[4] = {0, 4096, 5120, 5376};

#pragma unroll
    for (int it = 0; it < 16; it++) {
        const int e = tid + it * 256;           // e < 4096
        const int pt = e & 127;
        const int px = (e >> 7) & 7;
        const int lvl = e >> 10;
        if (pt < 100) {
            const int W2 = 64 >> lvl;
            const float scale = 1.0f / (float)(1 << lvl);
            const float x = s_cx[px] * scale;
            const float y = s_cy[px] * scale;
            const int x0 = (int)floorf(x);
            const int y0 = (int)floorf(y);
            const int gi = pt / 10;
            const int gj = pt - gi * 10;
            const int gx = x0 - 4 + gj;
            const int gy = y0 - 4 + gi;
            float v = 0.0f;
            if ((unsigned)gx < (unsigned)W2 && (unsigned)gy < (unsigned)W2)
                v = __half2float(g_corrh[((size_t)b * 4096 + hw + px) * CORR_COLS +
                                         lvl_base[lvl] + gy * W2 + gx]);
            dots[lvl][px][pt] = v;
        }
    }
    __syncthreads();

#pragma unroll
    for (int it = 0; it < 11; it++) {
        const int e = tid + it * 256;
        if (e < 2592) {
            const int lvl = e / 648;
            const int r = e - lvl * 648;
            const int k = r >> 3;
            const int px = r & 7;
            const int oi = k / 9;
            const int oj = k - oi * 9;
            const float scale = 1.0f / (float)(1 << lvl);
            const float x = s_cx[px] * scale;
            const float y = s_cy[px] * scale;
            const float fx = x - floorf(x);
            const float fy = y - floorf(y);
            const float w00 = (1.0f - fx) * (1.0f - fy);
            const float w10 = fx * (1.0f - fy);
            const float w01 = (1.0f - fx) * fy;
            const float w11 = fx * fy;
            const int base = oi * 10 + oj;
            const float* dp = dots[lvl][px];
            const float val = w00 * dp[base]      + w10 * dp[base + 1] +
                              w01 * dp[base + 10] + w11 * dp[base + 11];
            out[(size_t)(b * 324 + lvl * 81 + k) * 4096 + hw + px] = val * 0.0625f;
        }
    }
}

// ---------------------------------------------------------------------------
// Inputs: fmap1, fmap2_0..3, coords. Output [2,324,64,64] fp32.
// ---------------------------------------------------------------------------
extern "C" void kernel_launch(void* const* d_in, const int* in_sizes, int n_in,
                              void* d_out, int out_size) {
    const float* f1 = (const float*)d_in[0];
    const float* f2_0 = (const float*)d_in[1];
    const float* f2_1 = (const float*)d_in[2];
    const float* f2_2 = (const float*)d_in[3];
    const float* f2_3 = (const float*)d_in[4];
    const float* coords = (const float*)d_in[5];
    float* out = (float*)d_out;

    static bool attr_done = false;
    if (!attr_done) {
        cudaFuncSetAttribute(gemm_kernel, cudaFuncAttributeMaxDynamicSharedMemorySize,
                             GEMM_SMEM);
        attr_done = true;
    }

    tconv_kernel<<<dim3(306, 2, 2), 256>>>(f1, f2_0, f2_1, f2_2, f2_3, coords);
    gemm_kernel<<<dim3(43, 32, 2), 128, GEMM_SMEM>>>();
    gather_kernel<<<1024, 256>>>(coords, out);
}

// round 15
// speedup vs baseline: 1.3680x; 1.0119x over previous
#include <cuda_runtime.h>
#include <cuda_fp16.h>
#include <cstdint>
#include <cstddef>

// ---------------------------------------------------------------------------
// Scratch:
//   g_fh: f1h [2][4096][256] fp16 at 0; f2h [2][5504][256] fp16 at 2,097,152
//         (f2 level row bases 0,4096,5120,5376; rows 5440..5503 stay zero)
//   g_corrh: [2][4096][5504] fp16 correlation volume
//   g_mask: per (b, m-tile) bitmask of needed n-tiles (43 bits used)
// ---------------------------------------------------------------------------
#define F1H_OFF ((size_t)0)
#define F2H_OFF ((size_t)2097152)
#define F2_BSTRIDE ((size_t)1409024)   // 5504*256
#define CORR_COLS 5504
__device__ __half g_fh[4915200];
__device__ __half g_corrh[45088768];
__device__ unsigned long long g_mask[64];

__device__ __forceinline__ uint32_t smem_u32(const void* p) {
    uint32_t a;
    asm("{ .reg .u64 t; cvta.to.shared.u64 t, %1; cvt.u32.u64 %0, t; }"
        : "=r"(a) : "l"(p));
    return a;
}

// ---------------------------------------------------------------------------
// tconv v4 (round-14, exact): 32px x 128ch slab per block, MLP=4.
// ---------------------------------------------------------------------------
__global__ __launch_bounds__(256) void tconv_kernel(
    const float* __restrict__ f1, const float* __restrict__ f20,
    const float* __restrict__ f21, const float* __restrict__ f22,
    const float* __restrict__ f23, const float* __restrict__ coords) {
    __shared__ float tile[4][32][33];
    const int bx = blockIdx.x, bz = blockIdx.z;
    const int tid = threadIdx.x;

    if (bx >= 298) {
        if (blockIdx.y != 0 || bz != 0) return;
        const int gw = (bx - 298) * 8 + (tid >> 5);   // 0..63
        const int lane = tid & 31;
        const int b = gw >> 5, mt = gw & 31;
        const int lb[4] = {0, 4096, 5120, 5376};
        unsigned long long m = 0ULL;
#pragma unroll
        for (int j = 0; j < 4; j++) {
            const int hw = mt * 128 + j * 32 + lane;
            const float x = coords[(size_t)b * 8192 + hw];
            const float y = coords[(size_t)b * 8192 + 4096 + hw];
#pragma unroll
            for (int l = 0; l < 4; l++) {
                const int W2 = 64 >> l;
                const float s = 1.0f / (float)(1 << l);
                const int x0 = (int)floorf(x * s);
                const int y0 = (int)floorf(y * s);
                const int gx0 = max(x0 - 4, 0), gx1 = min(x0 + 5, W2 - 1);
                const int gy0 = max(y0 - 4, 0), gy1 = min(y0 + 5, W2 - 1);
                if (gx0 > gx1 || gy0 > gy1) continue;
                const int t0 = (lb[l] + gy0 * W2 + gx0) >> 7;
                const int t1 = (lb[l] + gy1 * W2 + gx1) >> 7;
                m |= (((1ULL << (t1 - t0 + 1)) - 1ULL) << t0);
            }
        }
        unsigned lo = (unsigned)m, hi = (unsigned)(m >> 32);
#pragma unroll
        for (int o = 16; o; o >>= 1) {
            lo |= __shfl_xor_sync(0xffffffffu, lo, o);
            hi |= __shfl_xor_sync(0xffffffffu, hi, o);
        }
        if (lane == 0) g_mask[gw] = ((unsigned long long)hi << 32) | lo;
        return;
    }

    const float* src;
    int P, pBase;
    size_t dstOff, bStride;
    if (bx < 128)      { src = f1;  P = 4096; pBase = bx;       dstOff = F1H_OFF;                      bStride = 1048576; }
    else if (bx < 256) { src = f20; P = 4096; pBase = bx - 128; dstOff = F2H_OFF;                      bStride = F2_BSTRIDE; }
    else if (bx < 288) { src = f21; P = 1024; pBase = bx - 256; dstOff = F2H_OFF + (size_t)4096 * 256; bStride = F2_BSTRIDE; }
    else if (bx < 296) { src = f22; P = 256;  pBase = bx - 288; dstOff = F2H_OFF + (size_t)5120 * 256; bStride = F2_BSTRIDE; }
    else               { src = f23; P = 64;   pBase = bx - 296; dstOff = F2H_OFF + (size_t)5376 * 256; bStride = F2_BSTRIDE; }

    const float* s = src + (size_t)bz * 256 * P;
    __half* d = g_fh + dstOff + (size_t)bz * bStride;
    const int p0 = pBase * 32, c0 = blockIdx.y * 128;

    {
        const int cr = tid >> 3, p4 = (tid & 7) * 4;
        float4 v[4];
#pragma unroll
        for (int k = 0; k < 4; k++)
            v[k] = *(const float4*)(s + (size_t)(c0 + k * 32 + cr) * P + p0 + p4);
#pragma unroll
        for (int k = 0; k < 4; k++) {
            tile[k][cr][p4] = v[k].x; tile[k][cr][p4 + 1] = v[k].y;
            tile[k][cr][p4 + 2] = v[k].z; tile[k][cr][p4 + 3] = v[k].w;
        }
    }
    __syncthreads();

    {
        const int w = tid >> 5, l = tid & 31;
        const int px = 4 * w + (l >> 3), cq = l & 7;
        __half* drow = d + (size_t)(p0 + px) * 256 + c0 + 4 * cq;
#pragma unroll
        for (int k = 0; k < 4; k++) {
            const __half2 h0 = __floats2half2_rn(tile[k][4 * cq][px],     tile[k][4 * cq + 1][px]);
            const __half2 h1 = __floats2half2_rn(tile[k][4 * cq + 2][px], tile[k][4 * cq + 3][px]);
            uint2 u;
            u.x = *(const uint32_t*)&h0;
            u.y = *(const uint32_t*)&h1;
            *(uint2*)(drow + k * 32) = u;
        }
    }
}

// ---------------------------------------------------------------------------
// GEMM (round-9 version, exact): 128x128 tile, K=256 in 4 chunks of 64,
// cp.async 3-stage pipeline, 4 warps (2Mx2N, warp tile 64x64),
// 96KB smem -> 2 CTAs/SM.
// ---------------------------------------------------------------------------
#define STAGE_BYTES 32768
#define GEMM_SMEM   (3 * STAGE_BYTES)   // 98304

__device__ __forceinline__ void ldsm_x4(uint32_t (&r)[4], uint32_t addr) {
    asm volatile("ldmatrix.sync.aligned.m8n8.x4.shared.b16 {%0,%1,%2,%3}, [%4];"
                 : "=r"(r[0]), "=r"(r[1]), "=r"(r[2]), "=r"(r[3]) : "r"(addr));
}
__device__ __forceinline__ void mma16816(float (&d)[4], const uint32_t (&a)[4],
                                         uint32_t b0, uint32_t b1) {
    asm volatile(
        "mma.sync.aligned.m16n8k16.row.col.f32.f16.f16.f32 "
        "{%0,%1,%2,%3},{%4,%5,%6,%7},{%8,%9},{%0,%1,%2,%3};"
        : "+f"(d[0]), "+f"(d[1]), "+f"(d[2]), "+f"(d[3])
        : "r"(a[0]), "r"(a[1]), "r"(a[2]), "r"(a[3]), "r"(b0), "r"(b1));
}

__device__ __forceinline__ uint32_t sw_addr(uint32_t base, int row, int chunk) {
    return base + (uint32_t)row * 128u + (uint32_t)((chunk ^ (row & 7)) << 4);
}

__device__ __forceinline__ void load_chunk(const __half* __restrict__ A,
                                           const __half* __restrict__ B,
                                           uint32_t sbase, int stage, int ck, int tid) {
    const uint32_t aoff = sbase + stage * STAGE_BYTES;
    const uint32_t boff = aoff + 16384;
#pragma unroll
    for (int q = tid; q < 1024; q += 128) {
        const int r = q >> 3, c = q & 7;
        const uint32_t sa = sw_addr(aoff, r, c);
        const uint32_t sb = sw_addr(boff, r, c);
        const __half* ga = A + (size_t)r * 256 + ck * 64 + c * 8;
        const __half* gb = B + (size_t)r * 256 + ck * 64 + c * 8;
        asm volatile("cp.async.cg.shared.global [%0], [%1], 16;" :: "r"(sa), "l"(ga));
        asm volatile("cp.async.cg.shared.global [%0], [%1], 16;" :: "r"(sb), "l"(gb));
    }
    asm volatile("cp.async.commit_group;" ::: "memory");
}

__global__ void __launch_bounds__(128, 2) gemm_kernel() {
    const int nt = blockIdx.x, mt = blockIdx.y, b = blockIdx.z;
    if (!((g_mask[b * 32 + mt] >> nt) & 1ULL)) return;

    extern __shared__ char smraw[];
    const uint32_t sbase = smem_u32(smraw);
    const int tid = threadIdx.x, warp = tid >> 5, lane = tid & 31;

    const __half* A = g_fh + F1H_OFF + ((size_t)b * 4096 + (size_t)mt * 128) * 256;
    const __half* B = g_fh + F2H_OFF + (size_t)b * F2_BSTRIDE + (size_t)nt * 128 * 256;

    load_chunk(A, B, sbase, 0, 0, tid);
    load_chunk(A, B, sbase, 1, 1, tid);

    const int wm = (warp & 1) * 64;
    const int wn = (warp >> 1) * 64;
    const int row_in = lane & 7;
    const int mat = lane >> 3;

    float acc[4][8][4];
#pragma unroll
    for (int mi = 0; mi < 4; mi++)
#pragma unroll
        for (int ni = 0; ni < 8; ni++)
#pragma unroll
            for (int j = 0; j < 4; j++) acc[mi][ni][j] = 0.0f;

#pragma unroll
    for (int ck = 0; ck < 4; ck++) {
        if (ck < 3) asm volatile("cp.async.wait_group 1;" ::: "memory");
        else        asm volatile("cp.async.wait_group 0;" ::: "memory");
        __syncthreads();
        if (ck + 2 < 4) load_chunk(A, B, sbase, (ck + 2) % 3, ck + 2, tid);

        const uint32_t aT = sbase + (ck % 3) * STAGE_BYTES;
        const uint32_t bT = aT + 16384;

#pragma unroll
        for (int ks = 0; ks < 4; ks++) {
            uint32_t af[4][4];
#pragma unroll
            for (int mi = 0; mi < 4; mi++) {
                const int row = wm + mi * 16 + (mat & 1) * 8 + row_in;
                ldsm_x4(af[mi], sw_addr(aT, row, ks * 2 + (mat >> 1)));
            }
            uint32_t bf[4][4];
#pragma unroll
            for (int bi = 0; bi < 4; bi++) {
                const int nrow = wn + bi * 16 + (mat >> 1) * 8 + row_in;
                ldsm_x4(bf[bi], sw_addr(bT, nrow, ks * 2 + (mat & 1)));
            }
#pragma unroll
            for (int mi = 0; mi < 4; mi++)
#pragma unroll
                for (int ni = 0; ni < 8; ni++) {
                    const uint32_t* bb = bf[ni >> 1];
                    if (ni & 1) mma16816(acc[mi][ni], af[mi], bb[2], bb[3]);
                    else        mma16816(acc[mi][ni], af[mi], bb[0], bb[1]);
                }
        }
    }

    const int g = lane >> 2, tg = lane & 3;
    __half* crow = g_corrh + ((size_t)b * 4096 + (size_t)mt * 128) * CORR_COLS +
                   (size_t)nt * 128;
#pragma unroll
    for (int mi = 0; mi < 4; mi++) {
#pragma unroll
        for (int ni = 0; ni < 8; ni++) {
            const int rm = wm + mi * 16 + g;
            const int cn = wn + ni * 8 + tg * 2;
            *(__half2*)(crow + (size_t)rm * CORR_COLS + cn) =
                __floats2half2_rn(acc[mi][ni][0], acc[mi][ni][1]);
            *(__half2*)(crow + (size_t)(rm + 8) * CORR_COLS + cn) =
                __floats2half2_rn(acc[mi][ni][2], acc[mi][ni][3]);
        }
    }
}

// ---------------------------------------------------------------------------
// Gather v3: pair-vectorized loads. 50 pairs per (px,lvl); even-parity warps
// use one aligned LDG.32 per pair (validity all-or-nothing since W2 even),
// odd-parity warps use two masked LDG.16. Warp-uniform branch (one (px,lvl)
// per warp). Combine phase unchanged.
// ---------------------------------------------------------------------------
__global__ __launch_bounds__(256) void gather_kernel(const float* __restrict__ coords,
                                                     float* __restrict__ out) {
    __shared__ __align__(16) float dots[4][8][104];
    __shared__ float s_cx[8], s_cy[8];

    const int tid = threadIdx.x;
    const int pix0 = blockIdx.x * 8;
    const int b = pix0 >> 12;
    const int hw = pix0 & 4095;

    if (tid < 8) {
        s_cx[tid] = coords[(size_t)b * 8192 + hw + tid];
        s_cy[tid] = coords[(size_t)b * 8192 + 4096 + hw + tid];
    }
    __syncthreads();

    const int lvl_base[4] = {0, 4096, 5120, 5376};

    // Load: slot space = lvl(4) x px(8) x pair(64, 50 active) = 2048, 8 iters.
#pragma unroll
    for (int it = 0; it < 8; it++) {
        const int e = tid + it * 256;          // < 2048
        const int pp = e & 63;
        const int px = (e >> 6) & 7;
        const int lvl = e >> 9;
        if (pp < 50) {
            const int W2 = 64 >> lvl;
            const float scale = 1.0f / (float)(1 << lvl);
            const float x = s_cx[px] * scale;
            const float y = s_cy[px] * scale;
            const int x0 = (int)floorf(x);
            const int y0 = (int)floorf(y);
            const int gi = pp / 5;             // 0..9 (window row)
            const int pj = pp - gi * 5;        // 0..4 (pair in row)
            const int gy = y0 - 4 + gi;
            const int gx = x0 - 4 + 2 * pj;
            const bool rowv = (unsigned)gy < (unsigned)W2;
            const int gyc = rowv ? gy : 0;
            const __half* rowp = g_corrh + ((size_t)b * 4096 + hw + px) * CORR_COLS +
                                 lvl_base[lvl] + gyc * W2;
            float v0 = 0.0f, v1 = 0.0f;
            if (((x0 - 4) & 1) == 0) {
                // aligned pair: valid iff 0 <= gx < W2 (then gx+1 < W2 too)
                const bool pv = rowv && ((unsigned)gx < (unsigned)W2);
                const __half2 h = *(const __half2*)(rowp + (pv ? gx : 0));
                if (pv) { v0 = __half2float(__low2half(h)); v1 = __half2float(__high2half(h)); }
            } else {
                const bool av = rowv && ((unsigned)gx < (unsigned)W2);
                const bool bv = rowv && ((unsigned)(gx + 1) < (unsigned)W2);
                const __half ha = rowp[av ? gx : 0];
                const __half hb = rowp[bv ? (gx + 1) : 0];
                if (av) v0 = __half2float(ha);
                if (bv) v1 = __half2float(hb);
            }
            const int pt = gi * 10 + 2 * pj;   // even
            *(float2*)&dots[lvl][px][pt] = make_float2(v0, v1);
        }
    }
    __syncthreads();

    // Combine: 4 lvl x 81 offsets x 8 px = 2592 outputs.
#pragma unroll
    for (int it = 0; it < 11; it++) {
        const int e = tid + it * 256;
        if (e < 2592) {
            const int lvl = e / 648;
            const int r = e - lvl * 648;
            const int k = r >> 3;
            const int px = r & 7;
            const int oi = k / 9;
            const int oj = k - oi * 9;
            const float scale = 1.0f / (float)(1 << lvl);
            const float x = s_cx[px] * scale;
            const float y = s_cy[px] * scale;
            const float fx = x - floorf(x);
            const float fy = y - floorf(y);
            const float w00 = (1.0f - fx) * (1.0f - fy);
            const float w10 = fx * (1.0f - fy);
            const float w01 = (1.0f - fx) * fy;
            const float w11 = fx * fy;
            const int base = oi * 10 + oj;
            const float* dp = dots[lvl][px];
            const float val = w00 * dp[base]      + w10 * dp[base + 1] +
                              w01 * dp[base + 10] + w11 * dp[base + 11];
            out[(size_t)(b * 324 + lvl * 81 + k) * 4096 + hw + px] = val * 0.0625f;
        }
    }
}

// ---------------------------------------------------------------------------
// Inputs: fmap1, fmap2_0..3, coords. Output [2,324,64,64] fp32.
// ---------------------------------------------------------------------------
extern "C" void kernel_launch(void* const* d_in, const int* in_sizes, int n_in,
                              void* d_out, int out_size) {
    const float* f1 = (const float*)d_in[0];
    const float* f2_0 = (const float*)d_in[1];
    const float* f2_1 = (const float*)d_in[2];
    const float* f2_2 = (const float*)d_in[3];
    const float* f2_3 = (const float*)d_in[4];
    const float* coords = (const float*)d_in[5];
    float* out = (float*)d_out;

    static bool attr_done = false;
    if (!attr_done) {
        cudaFuncSetAttribute(gemm_kernel, cudaFuncAttributeMaxDynamicSharedMemorySize,
                             GEMM_SMEM);
        attr_done = true;
    }

    tconv_kernel<<<dim3(306, 2, 2), 256>>>(f1, f2_0, f2_1, f2_2, f2_3, coords);
    gemm_kernel<<<dim3(43, 32, 2), 128, GEMM_SMEM>>>();
    gather_kernel<<<1024, 256>>>(coords, out);
}

// round 16
// speedup vs baseline: 1.5443x; 1.1289x over previous
#include <cuda_runtime.h>
#include <cuda_fp16.h>
#include <cstdint>
#include <cstddef>

// ---------------------------------------------------------------------------
// Scratch:
//   g_fh: f1h [2][4096][256] fp16 at 0; f2h [2][5504][256] fp16 at 2,097,152
//         (f2 level row bases 0,4096,5120,5376; rows 5440..5503 stay zero)
//   g_corrh: [2][4096][5504] fp16 correlation volume
//   g_mask: per (b, m-tile) bitmask of needed n-tiles (43 bits used)
// ---------------------------------------------------------------------------
#define F1H_OFF ((size_t)0)
#define F2H_OFF ((size_t)2097152)
#define F2_BSTRIDE ((size_t)1409024)   // 5504*256
#define CORR_COLS 5504
__device__ __half g_fh[4915200];
__device__ __half g_corrh[45088768];
__device__ unsigned long long g_mask[64];

__device__ __forceinline__ uint32_t smem_u32(const void* p) {
    uint32_t a;
    asm("{ .reg .u64 t; cvta.to.shared.u64 t, %1; cvt.u32.u64 %0, t; }"
        : "=r"(a) : "l"(p));
    return a;
}

// ---------------------------------------------------------------------------
// tconv v4 (round-14, exact): 32px x 128ch slab per block, MLP=4.
// ---------------------------------------------------------------------------
__global__ __launch_bounds__(256) void tconv_kernel(
    const float* __restrict__ f1, const float* __restrict__ f20,
    const float* __restrict__ f21, const float* __restrict__ f22,
    const float* __restrict__ f23, const float* __restrict__ coords) {
    __shared__ float tile[4][32][33];
    const int bx = blockIdx.x, bz = blockIdx.z;
    const int tid = threadIdx.x;

    if (bx >= 298) {
        if (blockIdx.y != 0 || bz != 0) return;
        const int gw = (bx - 298) * 8 + (tid >> 5);   // 0..63
        const int lane = tid & 31;
        const int b = gw >> 5, mt = gw & 31;
        const int lb[4] = {0, 4096, 5120, 5376};
        unsigned long long m = 0ULL;
#pragma unroll
        for (int j = 0; j < 4; j++) {
            const int hw = mt * 128 + j * 32 + lane;
            const float x = coords[(size_t)b * 8192 + hw];
            const float y = coords[(size_t)b * 8192 + 4096 + hw];
#pragma unroll
            for (int l = 0; l < 4; l++) {
                const int W2 = 64 >> l;
                const float s = 1.0f / (float)(1 << l);
                const int x0 = (int)floorf(x * s);
                const int y0 = (int)floorf(y * s);
                const int gx0 = max(x0 - 4, 0), gx1 = min(x0 + 5, W2 - 1);
                const int gy0 = max(y0 - 4, 0), gy1 = min(y0 + 5, W2 - 1);
                if (gx0 > gx1 || gy0 > gy1) continue;
                const int t0 = (lb[l] + gy0 * W2 + gx0) >> 7;
                const int t1 = (lb[l] + gy1 * W2 + gx1) >> 7;
                m |= (((1ULL << (t1 - t0 + 1)) - 1ULL) << t0);
            }
        }
        unsigned lo = (unsigned)m, hi = (unsigned)(m >> 32);
#pragma unroll
        for (int o = 16; o; o >>= 1) {
            lo |= __shfl_xor_sync(0xffffffffu, lo, o);
            hi |= __shfl_xor_sync(0xffffffffu, hi, o);
        }
        if (lane == 0) g_mask[gw] = ((unsigned long long)hi << 32) | lo;
        return;
    }

    const float* src;
    int P, pBase;
    size_t dstOff, bStride;
    if (bx < 128)      { src = f1;  P = 4096; pBase = bx;       dstOff = F1H_OFF;                      bStride = 1048576; }
    else if (bx < 256) { src = f20; P = 4096; pBase = bx - 128; dstOff = F2H_OFF;                      bStride = F2_BSTRIDE; }
    else if (bx < 288) { src = f21; P = 1024; pBase = bx - 256; dstOff = F2H_OFF + (size_t)4096 * 256; bStride = F2_BSTRIDE; }
    else if (bx < 296) { src = f22; P = 256;  pBase = bx - 288; dstOff = F2H_OFF + (size_t)5120 * 256; bStride = F2_BSTRIDE; }
    else               { src = f23; P = 64;   pBase = bx - 296; dstOff = F2H_OFF + (size_t)5376 * 256; bStride = F2_BSTRIDE; }

    const float* s = src + (size_t)bz * 256 * P;
    __half* d = g_fh + dstOff + (size_t)bz * bStride;
    const int p0 = pBase * 32, c0 = blockIdx.y * 128;

    {
        const int cr = tid >> 3, p4 = (tid & 7) * 4;
        float4 v[4];
#pragma unroll
        for (int k = 0; k < 4; k++)
            v[k] = *(const float4*)(s + (size_t)(c0 + k * 32 + cr) * P + p0 + p4);
#pragma unroll
        for (int k = 0; k < 4; k++) {
            tile[k][cr][p4] = v[k].x; tile[k][cr][p4 + 1] = v[k].y;
            tile[k][cr][p4 + 2] = v[k].z; tile[k][cr][p4 + 3] = v[k].w;
        }
    }
    __syncthreads();

    {
        const int w = tid >> 5, l = tid & 31;
        const int px = 4 * w + (l >> 3), cq = l & 7;
        __half* drow = d + (size_t)(p0 + px) * 256 + c0 + 4 * cq;
#pragma unroll
        for (int k = 0; k < 4; k++) {
            const __half2 h0 = __floats2half2_rn(tile[k][4 * cq][px],     tile[k][4 * cq + 1][px]);
            const __half2 h1 = __floats2half2_rn(tile[k][4 * cq + 2][px], tile[k][4 * cq + 3][px]);
            uint2 u;
            u.x = *(const uint32_t*)&h0;
            u.y = *(const uint32_t*)&h1;
            *(uint2*)(drow + k * 32) = u;
        }
    }
}

// ---------------------------------------------------------------------------
// GEMM: mainloop = round-9 exact. Epilogue v2: stage acc into smem fp16
// [128][136] (conflict-free STS), then warp-cooperative 256B-row copy-out
// with fully coalesced STG.128.
// ---------------------------------------------------------------------------
#define STAGE_BYTES 32768
#define GEMM_SMEM   (3 * STAGE_BYTES)   // 98304
#define EP_ROW 136                      // halves; 68 words -> STS banks (4g+tg)%32

__device__ __forceinline__ void ldsm_x4(uint32_t (&r)[4], uint32_t addr) {
    asm volatile("ldmatrix.sync.aligned.m8n8.x4.shared.b16 {%0,%1,%2,%3}, [%4];"
                 : "=r"(r[0]), "=r"(r[1]), "=r"(r[2]), "=r"(r[3]) : "r"(addr));
}
__device__ __forceinline__ void mma16816(float (&d)[4], const uint32_t (&a)[4],
                                         uint32_t b0, uint32_t b1) {
    asm volatile(
        "mma.sync.aligned.m16n8k16.row.col.f32.f16.f16.f32 "
        "{%0,%1,%2,%3},{%4,%5,%6,%7},{%8,%9},{%0,%1,%2,%3};"
        : "+f"(d[0]), "+f"(d[1]), "+f"(d[2]), "+f"(d[3])
        : "r"(a[0]), "r"(a[1]), "r"(a[2]), "r"(a[3]), "r"(b0), "r"(b1));
}

__device__ __forceinline__ uint32_t sw_addr(uint32_t base, int row, int chunk) {
    return base + (uint32_t)row * 128u + (uint32_t)((chunk ^ (row & 7)) << 4);
}

__device__ __forceinline__ void load_chunk(const __half* __restrict__ A,
                                           const __half* __restrict__ B,
                                           uint32_t sbase, int stage, int ck, int tid) {
    const uint32_t aoff = sbase + stage * STAGE_BYTES;
    const uint32_t boff = aoff + 16384;
#pragma unroll
    for (int q = tid; q < 1024; q += 128) {
        const int r = q >> 3, c = q & 7;
        const uint32_t sa = sw_addr(aoff, r, c);
        const uint32_t sb = sw_addr(boff, r, c);
        const __half* ga = A + (size_t)r * 256 + ck * 64 + c * 8;
        const __half* gb = B + (size_t)r * 256 + ck * 64 + c * 8;
        asm volatile("cp.async.cg.shared.global [%0], [%1], 16;" :: "r"(sa), "l"(ga));
        asm volatile("cp.async.cg.shared.global [%0], [%1], 16;" :: "r"(sb), "l"(gb));
    }
    asm volatile("cp.async.commit_group;" ::: "memory");
}

__global__ void __launch_bounds__(128, 2) gemm_kernel() {
    const int nt = blockIdx.x, mt = blockIdx.y, b = blockIdx.z;
    if (!((g_mask[b * 32 + mt] >> nt) & 1ULL)) return;

    extern __shared__ char smraw[];
    const uint32_t sbase = smem_u32(smraw);
    const int tid = threadIdx.x, warp = tid >> 5, lane = tid & 31;

    const __half* A = g_fh + F1H_OFF + ((size_t)b * 4096 + (size_t)mt * 128) * 256;
    const __half* B = g_fh + F2H_OFF + (size_t)b * F2_BSTRIDE + (size_t)nt * 128 * 256;

    load_chunk(A, B, sbase, 0, 0, tid);
    load_chunk(A, B, sbase, 1, 1, tid);

    const int wm = (warp & 1) * 64;
    const int wn = (warp >> 1) * 64;
    const int row_in = lane & 7;
    const int mat = lane >> 3;

    float acc[4][8][4];
#pragma unroll
    for (int mi = 0; mi < 4; mi++)
#pragma unroll
        for (int ni = 0; ni < 8; ni++)
#pragma unroll
            for (int j = 0; j < 4; j++) acc[mi][ni][j] = 0.0f;

#pragma unroll
    for (int ck = 0; ck < 4; ck++) {
        if (ck < 3) asm volatile("cp.async.wait_group 1;" ::: "memory");
        else        asm volatile("cp.async.wait_group 0;" ::: "memory");
        __syncthreads();
        if (ck + 2 < 4) load_chunk(A, B, sbase, (ck + 2) % 3, ck + 2, tid);

        const uint32_t aT = sbase + (ck % 3) * STAGE_BYTES;
        const uint32_t bT = aT + 16384;

#pragma unroll
        for (int ks = 0; ks < 4; ks++) {
            uint32_t af[4][4];
#pragma unroll
            for (int mi = 0; mi < 4; mi++) {
                const int row = wm + mi * 16 + (mat & 1) * 8 + row_in;
                ldsm_x4(af[mi], sw_addr(aT, row, ks * 2 + (mat >> 1)));
            }
            uint32_t bf[4][4];
#pragma unroll
            for (int bi = 0; bi < 4; bi++) {
                const int nrow = wn + bi * 16 + (mat >> 1) * 8 + row_in;
                ldsm_x4(bf[bi], sw_addr(bT, nrow, ks * 2 + (mat & 1)));
            }
#pragma unroll
            for (int mi = 0; mi < 4; mi++)
#pragma unroll
                for (int ni = 0; ni < 8; ni++) {
                    const uint32_t* bb = bf[ni >> 1];
                    if (ni & 1) mma16816(acc[mi][ni], af[mi], bb[2], bb[3]);
                    else        mma16816(acc[mi][ni], af[mi], bb[0], bb[1]);
                }
        }
    }

    // ---- Epilogue v2: pipeline fully drained; reuse stage smem ----
    __syncthreads();
    __half* eb = (__half*)smraw;          // [128][EP_ROW] halves = 34816 B
    {
        const int g = lane >> 2, tg = lane & 3;
#pragma unroll
        for (int mi = 0; mi < 4; mi++) {
#pragma unroll
            for (int ni = 0; ni < 8; ni++) {
                const int rm = wm + mi * 16 + g;
                const int cn = wn + ni * 8 + tg * 2;
                *(__half2*)&eb[rm * EP_ROW + cn] =
                    __floats2half2_rn(acc[mi][ni][0], acc[mi][ni][1]);
                *(__half2*)&eb[(rm + 8) * EP_ROW + cn] =
                    __floats2half2_rn(acc[mi][ni][2], acc[mi][ni][3]);
            }
        }
    }
    __syncthreads();
    {
        // warp w copies rows 32w..32w+31; lanes 0-15 row r, 16-31 row r+1,
        // each lane one 16B chunk -> STG.128 fully coalesced per row.
        const int half_ = lane >> 4;      // 0..1
        const int ch = lane & 15;         // 16B chunk in 256B row
        __half* crow = g_corrh + ((size_t)b * 4096 + (size_t)mt * 128) * CORR_COLS +
                       (size_t)nt * 128;
#pragma unroll
        for (int it = 0; it < 16; it++) {
            const int row = warp * 32 + it * 2 + half_;
            const uint4 v = *(const uint4*)&eb[row * EP_ROW + ch * 8];
            *(uint4*)(crow + (size_t)row * CORR_COLS + ch * 8) = v;
        }
    }
}

// ---------------------------------------------------------------------------
// Gather v3 (round-15, exact).
// ---------------------------------------------------------------------------
__global__ __launch_bounds__(256) void gather_kernel(const float* __restrict__ coords,
                                                     float* __restrict__ out) {
    __shared__ __align__(16) float dots[4][8][104];
    __shared__ float s_cx[8], s_cy[8];

    const int tid = threadIdx.x;
    const int pix0 = blockIdx.x * 8;
    const int b = pix0 >> 12;
    const int hw = pix0 & 4095;

    if (tid < 8) {
        s_cx[tid] = coords[(size_t)b * 8192 + hw + tid];
        s_cy[tid] = coords[(size_t)b * 8192 + 4096 + hw + tid];
    }
    __syncthreads();

    const int lvl_base[4] = {0, 4096, 5120, 5376};

#pragma unroll
    for (int it = 0; it < 8; it++) {
        const int e = tid + it * 256;          // < 2048
        const int pp = e & 63;
        const int px = (e >> 6) & 7;
        const int lvl = e >> 9;
        if (pp < 50) {
            const int W2 = 64 >> lvl;
            const float scale = 1.0f / (float)(1 << lvl);
            const float x = s_cx[px] * scale;
            const float y = s_cy[px] * scale;
            const int x0 = (int)floorf(x);
            const int y0 = (int)floorf(y);
            const int gi = pp / 5;
            const int pj = pp - gi * 5;
            const int gy = y0 - 4 + gi;
            const int gx = x0 - 4 + 2 * pj;
            const bool rowv = (unsigned)gy < (unsigned)W2;
            const int gyc = rowv ? gy : 0;
            const __half* rowp = g_corrh + ((size_t)b * 4096 + hw + px) * CORR_COLS +
                                 lvl_base[lvl] + gyc * W2;
            float v0 = 0.0f, v1 = 0.0f;
            if (((x0 - 4) & 1) == 0) {
                const bool pv = rowv && ((unsigned)gx < (unsigned)W2);
                const __half2 h = *(const __half2*)(rowp + (pv ? gx : 0));
                if (pv) { v0 = __half2float(__low2half(h)); v1 = __half2float(__high2half(h)); }
            } else {
                const bool av = rowv && ((unsigned)gx < (unsigned)W2);
                const bool bv = rowv && ((unsigned)(gx + 1) < (unsigned)W2);
                const __half ha = rowp[av ? gx : 0];
                const __half hb = rowp[bv ? (gx + 1) : 0];
                if (av) v0 = __half2float(ha);
                if (bv) v1 = __half2float(hb);
            }
            const int pt = gi * 10 + 2 * pj;
            *(float2*)&dots[lvl][px][pt] = make_float2(v0, v1);
        }
    }
    __syncthreads();

#pragma unroll
    for (int it = 0; it < 11; it++) {
        const int e = tid + it * 256;
        if (e < 2592) {
            const int lvl = e / 648;
            const int r = e - lvl * 648;
            const int k = r >> 3;
            const int px = r & 7;
            const int oi = k / 9;
            const int oj = k - oi * 9;
            const float scale = 1.0f / (float)(1 << lvl);
            const float x = s_cx[px] * scale;
            const float y = s_cy[px] * scale;
            const float fx = x - floorf(x);
            const float fy = y - floorf(y);
            const float w00 = (1.0f - fx) * (1.0f - fy);
            const float w10 = fx * (1.0f - fy);
            const float w01 = (1.0f - fx) * fy;
            const float w11 = fx * fy;
            const int base = oi * 10 + oj;
            const float* dp = dots[lvl][px];
            const float val = w00 * dp[base]      + w10 * dp[base + 1] +
                              w01 * dp[base + 10] + w11 * dp[base + 11];
            out[(size_t)(b * 324 + lvl * 81 + k) * 4096 + hw + px] = val * 0.0625f;
        }
    }
}

// ---------------------------------------------------------------------------
// Inputs: fmap1, fmap2_0..3, coords. Output [2,324,64,64] fp32.
// ---------------------------------------------------------------------------
extern "C" void kernel_launch(void* const* d_in, const int* in_sizes, int n_in,
                              void* d_out, int out_size) {
    const float* f1 = (const float*)d_in[0];
    const float* f2_0 = (const float*)d_in[1];
    const float* f2_1 = (const float*)d_in[2];
    const float* f2_2 = (const float*)d_in[3];
    const float* f2_3 = (const float*)d_in[4];
    const float* coords = (const float*)d_in[5];
    float* out = (float*)d_out;

    static bool attr_done = false;
    if (!attr_done) {
        cudaFuncSetAttribute(gemm_kernel, cudaFuncAttributeMaxDynamicSharedMemorySize,
                             GEMM_SMEM);
        attr_done = true;
    }

    tconv_kernel<<<dim3(306, 2, 2), 256>>>(f1, f2_0, f2_1, f2_2, f2_3, coords);
    gemm_kernel<<<dim3(43, 32, 2), 128, GEMM_SMEM>>>();
    gather_kernel<<<1024, 256>>>(coords, out);
}